// round 9
// baseline (speedup 1.0000x reference)
#include <cuda_runtime.h>
#include <cuda_bf16.h>
#include <stdint.h>

#define B_  256
#define K_  500
#define KH  250                   // j's per half-block
#define H_  152
#define W_  272
#define HW_ (H_ * W_)
#define ID_MAX 20000
#define TABLE_SIZE 20480          // >= ID_MAX+1, padded
#define NTHREADS 512
#define NBLOCKS  (B_ * 2)         // 2 blocks per batch -> 3.46 blocks/SM
#define FXP_SCALE 1048576.0f      // 2^20

__device__ unsigned long long g_num_acc  = 0ULL;
__device__ unsigned long long g_mask_acc = 0ULL;
__device__ unsigned           g_count    = 0;

__global__ __launch_bounds__(NTHREADS) void fwd_loss_fused(
    const float* __restrict__ flow,   // [B,2,H,W]
    const float* __restrict__ mask,   // [B,K]
    const int*   __restrict__ index,  // [B,K]
    const int*   __restrict__ ids,    // [B,K]
    const int*   __restrict__ index2, // [B,K]
    const int*   __restrict__ ids2,   // [B,K]
    float*       __restrict__ out)
{
    __shared__ uint16_t table[TABLE_SIZE];    // table[id] = k+1 ; 0 = absent (40KB)
    __shared__ float    s_mask[K_];
    __shared__ int      s_index[K_];
    __shared__ float    red_num[NTHREADS / 32];
    __shared__ float    red_msk[NTHREADS / 32];

    const int tid  = threadIdx.x;
    const int b    = blockIdx.x >> 1;         // batch element
    const int half = blockIdx.x & 1;          // which 250 j's this block probes

    // ---- Issue all coalesced scalar loads first (in flight during zeroing) ----
    int   id = 0, id2 = 0, i2 = 0, p = 0;
    float m = 0.0f;
    if (tid < K_) {                            // full build-side arrays
        const int g = b * K_ + tid;
        id = __ldg(&ids[g]);
        m  = __ldg(&mask[g]);
        p  = __ldg(&index[g]);
    }
    if (tid < KH) {                            // this block's probe half
        const int g2 = b * K_ + half * KH + tid;
        id2 = __ldg(&ids2[g2]);
        i2  = __ldg(&index2[g2]);
    }

    // Zero the direct table (overlaps with the loads above)
    {
        uint4* t4 = reinterpret_cast<uint4*>(table);
        #pragma unroll
        for (int i = tid; i < TABLE_SIZE * 2 / 16; i += NTHREADS)
            t4[i] = make_uint4(0, 0, 0, 0);
    }
    __syncthreads();

    // ---- Fill table + stage mask/index ----
    if (tid < K_) {
        table[id]    = (uint16_t)(tid + 1);   // id in 1..20000, unique
        s_mask[tid]  = m;
        s_index[tid] = p;
    }
    __syncthreads();

    // ---- Join + deferred gather (probe only this half's 250 j's) ----
    float lnum  = 0.0f;
    float lmask = (tid < KH) ? s_mask[half * KH + tid] : 0.0f;  // each j counted once
    if (tid < KH && (unsigned)(id2 - 1) < (unsigned)ID_MAX) {   // 1..20000 only
        int x1 = (int)table[id2];
        if (x1 != 0) {
            int   x  = x1 - 1;
            float mx = s_mask[x];
            float px = 0.0f, py = 0.0f;
            if (mx != 0.0f) {
                int pp = s_index[x];
                const float* fb = flow + (size_t)b * 2 * HW_;
                px = __ldg(&fb[pp]) * mx;           // channel 0 gather
                py = __ldg(&fb[HW_ + pp]) * mx;     // channel 1 gather
            }
            float vx = (float)(i2 % W_);
            float vy = (float)i2 / (float)W_;
            lnum = fabsf(px - vx) + fabsf(py - vy);
        }
    }

    // ---- Block reduction ----
    const int lane = tid & 31;
    const int warp = tid >> 5;
    #pragma unroll
    for (int off = 16; off > 0; off >>= 1) {
        lnum  += __shfl_down_sync(0xFFFFFFFFu, lnum,  off);
        lmask += __shfl_down_sync(0xFFFFFFFFu, lmask, off);
    }
    if (lane == 0) { red_num[warp] = lnum; red_msk[warp] = lmask; }
    __syncthreads();

    __shared__ bool s_last;
    if (warp == 0) {
        float n  = (lane < NTHREADS / 32) ? red_num[lane] : 0.0f;
        float mm = (lane < NTHREADS / 32) ? red_msk[lane] : 0.0f;
        #pragma unroll
        for (int off = 8; off > 0; off >>= 1) {
            n  += __shfl_down_sync(0xFFFFFFFFu, n,  off);
            mm += __shfl_down_sync(0xFFFFFFFFu, mm, off);
        }
        if (lane == 0) {
            // Deterministic order-independent accumulation: 64-bit fixed point.
            atomicAdd(&g_num_acc,  (unsigned long long)llrintf(n  * FXP_SCALE));
            atomicAdd(&g_mask_acc, (unsigned long long)llrintf(mm * FXP_SCALE));
            __threadfence();
            unsigned prev = atomicAdd(&g_count, 1u);
            s_last = (prev == NBLOCKS - 1);
        }
    }
    __syncthreads();

    // ---- Last block, thread 0: finalize from 2 scalars ----
    if (s_last && tid == 0) {
        __threadfence();
        unsigned long long un = atomicAdd(&g_num_acc,  0ULL);
        unsigned long long um = atomicAdd(&g_mask_acc, 0ULL);
        float nn = (float)((double)(long long)un / (double)FXP_SCALE);
        float mt = (float)((double)(long long)um / (double)FXP_SCALE);
        out[0] = nn / (2.0f * mt + 0.0001f);
        g_num_acc  = 0ULL;   // reset for next graph replay (deterministic)
        g_mask_acc = 0ULL;
        g_count    = 0;
    }
}

extern "C" void kernel_launch(void* const* d_in, const int* in_sizes, int n_in,
                              void* d_out, int out_size) {
    const float* flow   = (const float*)d_in[0];
    const float* mask   = (const float*)d_in[1];
    const int*   index  = (const int*)  d_in[2];
    const int*   ids    = (const int*)  d_in[3];
    const int*   index2 = (const int*)  d_in[4];
    const int*   ids2   = (const int*)  d_in[5];
    float* out = (float*)d_out;

    fwd_loss_fused<<<NBLOCKS, NTHREADS>>>(flow, mask, index, ids, index2, ids2, out);
}